// round 4
// baseline (speedup 1.0000x reference)
#include <cuda_runtime.h>

// Fused embedding, round 4: explicit gather batching.
//  - warp owns 32 consecutive rows, processed as 4 chunks of 8
//  - phase 1: 8 independent LDG.128 gathers into distinct regs (MLP=8/warp),
//    primary address chosen branch-free (selp) between num_weight row and cat row
//  - phase 2: numeric fixup (bias load + fma) for the ~10% numeric rows
//  - phase 3: 8 streaming stores

__global__ void __launch_bounds__(128) emb_fused_kernel(
    const int*    __restrict__ fid,      // [B*L]
    const float*  __restrict__ fval,     // [B*L]
    const float4* __restrict__ cat,      // [N_CAT, 32] as float4
    const float4* __restrict__ w,        // [N_NUM, 32]
    const float4* __restrict__ b,        // [N_NUM, 32]
    const int*    __restrict__ to_num,   // [VOCAB+1]
    const int*    __restrict__ to_cat,   // [VOCAB+1]
    float4*       __restrict__ out)      // [B*L, 32]
{
    const int lane = threadIdx.x & 31;
    const int warp_global = blockIdx.x * (blockDim.x >> 5) + (threadIdx.x >> 5);
    const long base = (long)warp_global * 32;

    // Per-lane scalar stage for row base+lane (coalesced; chain runs once, MLP=32)
    const long my_row = base + lane;
    const int   id  = __ldg(&fid[my_row]);
    const float v   = __ldg(&fval[my_row]);
    const int  nidx = __ldg(&to_num[id]);
    const int  cidx = __ldg(&to_cat[id]);

    // packed: numeric -> (nidx-1) | signbit ; categorical -> cidx (>= 0)
    const int packed = (nidx > 0) ? ((nidx - 1) | 0x80000000) : cidx;

    #pragma unroll
    for (int c = 0; c < 4; c++) {
        int   pp[8];
        float vv[8];
        float4 res[8];

        #pragma unroll
        for (int r = 0; r < 8; r++) {
            pp[r] = __shfl_sync(0xffffffffu, packed, c * 8 + r);
            vv[r] = __shfl_sync(0xffffffffu, v,      c * 8 + r);
        }

        // Phase 1: 8 independent primary gathers, branch-free addressing.
        #pragma unroll
        for (int r = 0; r < 8; r++) {
            const int p = pp[r];
            const long row = (long)(p & 0x7fffffff) * 32 + lane;
            const float4* src = (p < 0) ? (w + row) : (cat + row);
            res[r] = __ldg(src);
        }

        // Phase 2: numeric fixup (warp-uniform predicate per row; ~10% of rows).
        #pragma unroll
        for (int r = 0; r < 8; r++) {
            if (pp[r] < 0) {
                const float4 bv = __ldg(b + (long)(pp[r] & 0x7fffffff) * 32 + lane);
                res[r].x = fmaf(res[r].x, vv[r], bv.x);
                res[r].y = fmaf(res[r].y, vv[r], bv.y);
                res[r].z = fmaf(res[r].z, vv[r], bv.z);
                res[r].w = fmaf(res[r].w, vv[r], bv.w);
            }
        }

        // Phase 3: streaming stores (write-once output, don't pollute L2).
        #pragma unroll
        for (int r = 0; r < 8; r++)
            __stcs(&out[(base + c * 8 + r) * 32 + lane], res[r]);
    }
}

// Tail kernel (safety for n_rows % 128 != 0; unused for B*L = 262144)
__global__ void __launch_bounds__(128) emb_tail_kernel(
    const int*    __restrict__ fid,
    const float*  __restrict__ fval,
    const float4* __restrict__ cat,
    const float4* __restrict__ w,
    const float4* __restrict__ b,
    const int*    __restrict__ to_num,
    const int*    __restrict__ to_cat,
    float4*       __restrict__ out,
    int start_row, int n_rows)
{
    int row  = start_row + blockIdx.x * (blockDim.x >> 5) + (threadIdx.x >> 5);
    int lane = threadIdx.x & 31;
    if (row >= n_rows) return;
    int id   = __ldg(&fid[row]);
    int nidx = __ldg(&to_num[id]);
    float4 r;
    if (nidx > 0) {
        float v = __ldg(&fval[row]);
        long  o = (long)(nidx - 1) * 32 + lane;
        float4 wv = __ldg(&w[o]);
        float4 bv = __ldg(&b[o]);
        r.x = fmaf(wv.x, v, bv.x);
        r.y = fmaf(wv.y, v, bv.y);
        r.z = fmaf(wv.z, v, bv.z);
        r.w = fmaf(wv.w, v, bv.w);
    } else {
        int c = __ldg(&to_cat[id]);
        r = __ldg(&cat[(long)c * 32 + lane]);
    }
    __stcs(&out[(long)row * 32 + lane], r);
}

extern "C" void kernel_launch(void* const* d_in, const int* in_sizes, int n_in,
                              void* d_out, int out_size)
{
    const int*    fid    = (const int*)   d_in[0];
    const float*  fval   = (const float*) d_in[1];
    const float4* cat    = (const float4*)d_in[2];
    const float4* w      = (const float4*)d_in[3];
    const float4* b      = (const float4*)d_in[4];
    const int*    to_num = (const int*)   d_in[5];
    const int*    to_cat = (const int*)   d_in[6];
    float4*       out    = (float4*)      d_out;

    const int n_rows = in_sizes[0];                 // 262144
    const int rows_per_block = 4 * 32;              // 4 warps x 32 rows
    const int full_blocks = n_rows / rows_per_block;
    if (full_blocks > 0)
        emb_fused_kernel<<<full_blocks, 128>>>(fid, fval, cat, w, b, to_num, to_cat, out);
    const int done = full_blocks * rows_per_block;
    const int rem  = n_rows - done;
    if (rem > 0) {
        int tb = (rem + 3) / 4;
        emb_tail_kernel<<<tb, 128>>>(fid, fval, cat, w, b, to_num, to_cat, out, done, n_rows);
    }
}

// round 5
// speedup vs baseline: 1.0654x; 1.0654x over previous
#include <cuda_runtime.h>

// Fused embedding, round 5: software-pipelined gathers.
//  - warp owns 32 consecutive rows = 8 chunks of 4, double-buffered:
//    chunk c+1's gathers issue before chunk c's fixup+stores -> 4-8 loads
//    always in flight per warp while stores drain.
//  - all 32-bit index math (tables < 2GB, out < 2GB byte range)
//  - v shfl only on numeric fixup path (~10% of rows)

__global__ void __launch_bounds__(128) emb_fused_kernel(
    const int*    __restrict__ fid,      // [B*L]
    const float*  __restrict__ fval,     // [B*L]
    const float4* __restrict__ cat,      // [N_CAT, 32] as float4
    const float4* __restrict__ w,        // [N_NUM, 32]
    const float4* __restrict__ b,        // [N_NUM, 32]
    const int*    __restrict__ to_num,   // [VOCAB+1]
    const int*    __restrict__ to_cat,   // [VOCAB+1]
    float4*       __restrict__ out)      // [B*L, 32]
{
    const int lane = threadIdx.x & 31;
    const int warp_global = blockIdx.x * (blockDim.x >> 5) + (threadIdx.x >> 5);
    const int base = warp_global * 32;            // row index, < 2^18: fits int

    // Per-lane scalar stage for row base+lane (coalesced; chain runs once, MLP=32)
    const int   id  = __ldg(&fid[base + lane]);
    const float v   = __ldg(&fval[base + lane]);
    const int  nidx = __ldg(&to_num[id]);
    const int  cidx = __ldg(&to_cat[id]);

    // packed: numeric -> (nidx-1) | signbit ; categorical -> cidx (>= 0)
    const int packed = (nidx > 0) ? ((nidx - 1) | 0x80000000) : cidx;

    int    pp[2][4];
    float4 res[2][4];

    // Prologue: issue chunk 0's gathers.
    #pragma unroll
    for (int r = 0; r < 4; r++) {
        const int p = __shfl_sync(0xffffffffu, packed, r);
        pp[0][r] = p;
        const int idx = ((p & 0x7fffffff) << 5) + lane;   // float4 index, fits int
        res[0][r] = (p < 0) ? __ldg(w + idx) : __ldg(cat + idx);
    }

    #pragma unroll
    for (int c = 0; c < 8; c++) {
        const int cur = c & 1;
        const int nxt = cur ^ 1;

        // Issue next chunk's gathers first (keeps 8 loads in flight).
        if (c < 7) {
            #pragma unroll
            for (int r = 0; r < 4; r++) {
                const int p = __shfl_sync(0xffffffffu, packed, (c + 1) * 4 + r);
                pp[nxt][r] = p;
                const int idx = ((p & 0x7fffffff) << 5) + lane;
                res[nxt][r] = (p < 0) ? __ldg(w + idx) : __ldg(cat + idx);
            }
        }

        // Fixup current chunk (numeric rows only, warp-uniform predicate).
        #pragma unroll
        for (int r = 0; r < 4; r++) {
            const int p = pp[cur][r];
            if (p < 0) {
                const float vr = __shfl_sync(0xffffffffu, v, c * 4 + r);
                const float4 bv = __ldg(b + ((p & 0x7fffffff) << 5) + lane);
                res[cur][r].x = fmaf(res[cur][r].x, vr, bv.x);
                res[cur][r].y = fmaf(res[cur][r].y, vr, bv.y);
                res[cur][r].z = fmaf(res[cur][r].z, vr, bv.z);
                res[cur][r].w = fmaf(res[cur][r].w, vr, bv.w);
            }
        }

        // Store current chunk (streaming: write-once output).
        #pragma unroll
        for (int r = 0; r < 4; r++)
            __stcs(&out[((base + c * 4 + r) << 5) + lane], res[cur][r]);
    }
}

// Tail kernel (safety for n_rows % 128 != 0; unused for B*L = 262144)
__global__ void __launch_bounds__(128) emb_tail_kernel(
    const int*    __restrict__ fid,
    const float*  __restrict__ fval,
    const float4* __restrict__ cat,
    const float4* __restrict__ w,
    const float4* __restrict__ b,
    const int*    __restrict__ to_num,
    const int*    __restrict__ to_cat,
    float4*       __restrict__ out,
    int start_row, int n_rows)
{
    int row  = start_row + blockIdx.x * (blockDim.x >> 5) + (threadIdx.x >> 5);
    int lane = threadIdx.x & 31;
    if (row >= n_rows) return;
    int id   = __ldg(&fid[row]);
    int nidx = __ldg(&to_num[id]);
    float4 r;
    if (nidx > 0) {
        float v = __ldg(&fval[row]);
        long  o = (long)(nidx - 1) * 32 + lane;
        float4 wv = __ldg(&w[o]);
        float4 bv = __ldg(&b[o]);
        r.x = fmaf(wv.x, v, bv.x);
        r.y = fmaf(wv.y, v, bv.y);
        r.z = fmaf(wv.z, v, bv.z);
        r.w = fmaf(wv.w, v, bv.w);
    } else {
        int c = __ldg(&to_cat[id]);
        r = __ldg(&cat[(long)c * 32 + lane]);
    }
    __stcs(&out[(long)row * 32 + lane], r);
}

extern "C" void kernel_launch(void* const* d_in, const int* in_sizes, int n_in,
                              void* d_out, int out_size)
{
    const int*    fid    = (const int*)   d_in[0];
    const float*  fval   = (const float*) d_in[1];
    const float4* cat    = (const float4*)d_in[2];
    const float4* w      = (const float4*)d_in[3];
    const float4* b      = (const float4*)d_in[4];
    const int*    to_num = (const int*)   d_in[5];
    const int*    to_cat = (const int*)   d_in[6];
    float4*       out    = (float4*)      d_out;

    const int n_rows = in_sizes[0];                 // 262144
    const int rows_per_block = 4 * 32;              // 4 warps x 32 rows
    const int full_blocks = n_rows / rows_per_block;
    if (full_blocks > 0)
        emb_fused_kernel<<<full_blocks, 128>>>(fid, fval, cat, w, b, to_num, to_cat, out);
    const int done = full_blocks * rows_per_block;
    const int rem  = n_rows - done;
    if (rem > 0) {
        int tb = (rem + 3) / 4;
        emb_tail_kernel<<<tb, 128>>>(fid, fval, cat, w, b, to_num, to_cat, out, done, n_rows);
    }
}